// round 1
// baseline (speedup 1.0000x reference)
#include <cuda_runtime.h>

#define E_DIM   1024
#define N_HEADS 16
#define H_DIM   64
#define N_BATCH 2
#define SEQ_LEN 2048
#define M_TOT   (N_BATCH * SEQ_LEN)   // 4096

// Scratch (device globals: allocation-free per harness rules)
__device__ float g_Q[N_BATCH * N_HEADS * SEQ_LEN * H_DIM];
__device__ float g_K[N_BATCH * N_HEADS * SEQ_LEN * H_DIM];
__device__ float g_V[N_BATCH * N_HEADS * SEQ_LEN * H_DIM];
__device__ float g_attn[M_TOT * E_DIM];

// ---------------------------------------------------------------------------
// Tiled GEMM body: C[m,n] = sum_k A[m,k] * W[n,k] + bias[n]
// BM=BN=128, BK=16, 256 threads, 8x8 register tile per thread.
// remap=true scatters output into [B,H,S,D] layout for attention.
// ---------------------------------------------------------------------------
__device__ __forceinline__ void gemm_body(
    const float* __restrict__ A, const float* __restrict__ W,
    const float* __restrict__ bias, float* __restrict__ C, bool remap)
{
    __shared__ float As[16][132];   // [k][m], stride 132 floats = 528B (16B-divisible)
    __shared__ float Bs[16][132];   // [k][n]

    const int tid = threadIdx.x;
    const int m0 = blockIdx.y * 128;
    const int n0 = blockIdx.x * 128;
    const int ty = tid >> 4;        // 0..15 -> row group
    const int tx = tid & 15;        // 0..15 -> col group

    float acc[8][8];
#pragma unroll
    for (int i = 0; i < 8; i++)
#pragma unroll
        for (int j = 0; j < 8; j++) acc[i][j] = 0.0f;

    for (int k0 = 0; k0 < E_DIM; k0 += 16) {
#pragma unroll
        for (int r = 0; r < 2; r++) {
            int idx = tid + r * 256;          // 0..511
            int row = idx >> 2;               // 0..127
            int kc  = (idx & 3) << 2;         // 0,4,8,12
            float4 a = *(const float4*)(A + (size_t)(m0 + row) * E_DIM + k0 + kc);
            As[kc + 0][row] = a.x; As[kc + 1][row] = a.y;
            As[kc + 2][row] = a.z; As[kc + 3][row] = a.w;
            float4 b = *(const float4*)(W + (size_t)(n0 + row) * E_DIM + k0 + kc);
            Bs[kc + 0][row] = b.x; Bs[kc + 1][row] = b.y;
            Bs[kc + 2][row] = b.z; Bs[kc + 3][row] = b.w;
        }
        __syncthreads();
#pragma unroll
        for (int kk = 0; kk < 16; kk++) {
            float a[8], b[8];
            *(float4*)&a[0] = *(const float4*)&As[kk][ty * 8];
            *(float4*)&a[4] = *(const float4*)&As[kk][ty * 8 + 4];
            *(float4*)&b[0] = *(const float4*)&Bs[kk][tx * 8];
            *(float4*)&b[4] = *(const float4*)&Bs[kk][tx * 8 + 4];
#pragma unroll
            for (int i = 0; i < 8; i++)
#pragma unroll
                for (int j = 0; j < 8; j++)
                    acc[i][j] = fmaf(a[i], b[j], acc[i][j]);
        }
        __syncthreads();
    }

    float bi[8];
#pragma unroll
    for (int j = 0; j < 8; j++) bi[j] = bias[n0 + tx * 8 + j];

#pragma unroll
    for (int i = 0; i < 8; i++) {
        int m = m0 + ty * 8 + i;
        float4 v0 = make_float4(acc[i][0] + bi[0], acc[i][1] + bi[1],
                                acc[i][2] + bi[2], acc[i][3] + bi[3]);
        float4 v1 = make_float4(acc[i][4] + bi[4], acc[i][5] + bi[5],
                                acc[i][6] + bi[6], acc[i][7] + bi[7]);
        if (remap) {
            // n0+tx*8..+7 stays within one 64-aligned head block
            int b_ = m >> 11;                 // m / SEQ_LEN
            int s  = m & (SEQ_LEN - 1);
            int n  = n0 + tx * 8;
            int h  = n >> 6;
            int d  = n & 63;
            float* dst = C + (((size_t)(b_ * N_HEADS + h) * SEQ_LEN + s) * H_DIM) + d;
            *(float4*)dst = v0;
            *(float4*)(dst + 4) = v1;
        } else {
            float* dst = C + (size_t)m * E_DIM + n0 + tx * 8;
            *(float4*)dst = v0;
            *(float4*)(dst + 4) = v1;
        }
    }
}

__global__ __launch_bounds__(256, 2)
void qkv_kernel(const float* __restrict__ x,
                const float* __restrict__ wq, const float* __restrict__ bq,
                const float* __restrict__ wk, const float* __restrict__ bk,
                const float* __restrict__ wv, const float* __restrict__ bv)
{
    const float* W; const float* bias; float* C;
    if (blockIdx.z == 0)      { W = wq; bias = bq; C = g_Q; }
    else if (blockIdx.z == 1) { W = wk; bias = bk; C = g_K; }
    else                      { W = wv; bias = bv; C = g_V; }
    gemm_body(x, W, bias, C, true);
}

__global__ __launch_bounds__(256, 2)
void out_kernel(const float* __restrict__ wo, const float* __restrict__ bo,
                float* __restrict__ out)
{
    gemm_body(g_attn, wo, bo, out, false);
}

// ---------------------------------------------------------------------------
// Flash attention: one block per (bh, 64-row Q block). Online softmax.
// Threads 16x16: thread (ty,tx) owns S rows ty*4..+3 / cols tx*4..+3,
// and O rows ty*4..+3 / dims tx*4..+3.
// SMEM layouts (stride 68 floats = 272B, 16B-divisible for LDS.128):
//   Qs[d][i], Ks[d][j]  (transposed -> contiguous i/j reads)
//   Vs[j][d]            (natural)
//   Ps[j][i]            (transposed)
// ---------------------------------------------------------------------------
#define FL_SMEM_FLOATS (4 * 64 * 68)
#define FL_SMEM_BYTES  (FL_SMEM_FLOATS * 4)

__global__ __launch_bounds__(256)
void flash_kernel()
{
    extern __shared__ float sm[];
    float* Qs = sm;
    float* Ks = sm + 64 * 68;
    float* Vs = sm + 2 * 64 * 68;
    float* Ps = sm + 3 * 64 * 68;

    const int tid = threadIdx.x;
    const int ty = tid >> 4;
    const int tx = tid & 15;
    const int bh = blockIdx.y;
    const int q0 = blockIdx.x * 64;

    const float* Qp = g_Q + (size_t)bh * SEQ_LEN * H_DIM;
    const float* Kp = g_K + (size_t)bh * SEQ_LEN * H_DIM;
    const float* Vp = g_V + (size_t)bh * SEQ_LEN * H_DIM;

    // Load Q block transposed, fold in 1/sqrt(D) = 0.125
#pragma unroll
    for (int t = 0; t < 16; t++) {
        int idx = tid + t * 256;       // 0..4095
        int r = idx >> 6, d = idx & 63;
        Qs[d * 68 + r] = Qp[(size_t)(q0 + r) * H_DIM + d] * 0.125f;
    }

    float m_i[4], l_i[4], o[4][4];
#pragma unroll
    for (int i = 0; i < 4; i++) {
        m_i[i] = -1e30f; l_i[i] = 0.0f;
#pragma unroll
        for (int j = 0; j < 4; j++) o[i][j] = 0.0f;
    }
    __syncthreads();

    for (int kt = 0; kt < SEQ_LEN; kt += 64) {
        // Load K (transposed) and V (natural) tiles
#pragma unroll
        for (int t = 0; t < 16; t++) {
            int idx = tid + t * 256;
            int r = idx >> 6, d = idx & 63;
            Ks[d * 68 + r] = Kp[(size_t)(kt + r) * H_DIM + d];
            Vs[r * 68 + d] = Vp[(size_t)(kt + r) * H_DIM + d];
        }
        __syncthreads();

        // S = Q * K^T (scaled)
        float s4[4][4];
#pragma unroll
        for (int i = 0; i < 4; i++)
#pragma unroll
            for (int j = 0; j < 4; j++) s4[i][j] = 0.0f;

#pragma unroll 8
        for (int d = 0; d < 64; d++) {
            float4 a4 = *(const float4*)&Qs[d * 68 + ty * 4];
            float4 b4 = *(const float4*)&Ks[d * 68 + tx * 4];
            float av[4] = {a4.x, a4.y, a4.z, a4.w};
            float bv[4] = {b4.x, b4.y, b4.z, b4.w};
#pragma unroll
            for (int i = 0; i < 4; i++)
#pragma unroll
                for (int j = 0; j < 4; j++)
                    s4[i][j] = fmaf(av[i], bv[j], s4[i][j]);
        }

        // Online softmax (row reductions across the 16 tx lanes = warp half)
#pragma unroll
        for (int i = 0; i < 4; i++) {
            float mx = fmaxf(fmaxf(s4[i][0], s4[i][1]), fmaxf(s4[i][2], s4[i][3]));
#pragma unroll
            for (int off = 8; off >= 1; off >>= 1)
                mx = fmaxf(mx, __shfl_xor_sync(0xffffffffu, mx, off));
            float mn = fmaxf(m_i[i], mx);
            float corr = __expf(m_i[i] - mn);
            m_i[i] = mn;
            float p[4], rs = 0.0f;
#pragma unroll
            for (int j = 0; j < 4; j++) {
                p[j] = __expf(s4[i][j] - mn);
                rs += p[j];
            }
#pragma unroll
            for (int off = 8; off >= 1; off >>= 1)
                rs += __shfl_xor_sync(0xffffffffu, rs, off);
            l_i[i] = l_i[i] * corr + rs;
#pragma unroll
            for (int j = 0; j < 4; j++) o[i][j] *= corr;
#pragma unroll
            for (int j = 0; j < 4; j++)
                Ps[(tx * 4 + j) * 68 + ty * 4 + i] = p[j];
        }
        __syncthreads();

        // O += P * V
#pragma unroll 8
        for (int j = 0; j < 64; j++) {
            float4 p4 = *(const float4*)&Ps[j * 68 + ty * 4];
            float4 v4 = *(const float4*)&Vs[j * 68 + tx * 4];
            float pv[4] = {p4.x, p4.y, p4.z, p4.w};
            float vv[4] = {v4.x, v4.y, v4.z, v4.w};
#pragma unroll
            for (int i = 0; i < 4; i++)
#pragma unroll
                for (int jj = 0; jj < 4; jj++)
                    o[i][jj] = fmaf(pv[i], vv[jj], o[i][jj]);
        }
        __syncthreads();
    }

    // Write O/l into [B,S,E] layout (so out-proj is a plain GEMM)
    const int b_ = bh >> 4;
    const int h  = bh & 15;
#pragma unroll
    for (int i = 0; i < 4; i++) {
        float inv = 1.0f / l_i[i];
        int srow = q0 + ty * 4 + i;
        float* dst = g_attn + (size_t)(b_ * SEQ_LEN + srow) * E_DIM + h * H_DIM + tx * 4;
        *(float4*)dst = make_float4(o[i][0] * inv, o[i][1] * inv,
                                    o[i][2] * inv, o[i][3] * inv);
    }
}

// ---------------------------------------------------------------------------
extern "C" void kernel_launch(void* const* d_in, const int* in_sizes, int n_in,
                              void* d_out, int out_size)
{
    const float* x  = (const float*)d_in[0];
    const float* wq = (const float*)d_in[1];
    const float* bq = (const float*)d_in[2];
    const float* wk = (const float*)d_in[3];
    const float* bk = (const float*)d_in[4];
    const float* wv = (const float*)d_in[5];
    const float* bv = (const float*)d_in[6];
    const float* wo = (const float*)d_in[7];
    const float* bo = (const float*)d_in[8];
    float* out = (float*)d_out;

    cudaFuncSetAttribute(flash_kernel,
                         cudaFuncAttributeMaxDynamicSharedMemorySize, FL_SMEM_BYTES);

    dim3 gqkv(E_DIM / 128, M_TOT / 128, 3);
    qkv_kernel<<<gqkv, 256>>>(x, wq, bq, wk, bk, wv, bv);

    dim3 gfl(SEQ_LEN / 64, N_BATCH * N_HEADS);
    flash_kernel<<<gfl, 256, FL_SMEM_BYTES>>>();

    dim3 gout(E_DIM / 128, M_TOT / 128);
    out_kernel<<<gout, 256>>>(wo, bo, out);
}

// round 8
// speedup vs baseline: 1.3510x; 1.3510x over previous
#include <cuda_runtime.h>
#include <cuda_bf16.h>
#include <cstdint>

#define E_DIM   1024
#define N_HEADS 16
#define H_DIM   64
#define N_BATCH 2
#define SEQ_LEN 2048
#define M_TOT   (N_BATCH * SEQ_LEN)   // 4096

__device__ float g_Q[N_BATCH * N_HEADS * SEQ_LEN * H_DIM];
__device__ float g_K[N_BATCH * N_HEADS * SEQ_LEN * H_DIM];
__device__ float g_V[N_BATCH * N_HEADS * SEQ_LEN * H_DIM];
__device__ float g_attn[M_TOT * E_DIM];

// ---------------------------------------------------------------------------
// HMMA m16n8k16 bf16 (sm_80+ baseline PTX; legal on plain sm_103 target)
// D = A(16x16 row) * B(16x8 col) + D, fp32 accum.
// ---------------------------------------------------------------------------
__device__ __forceinline__ void mma_bf16(float* c, const uint32_t* a,
                                         const uint32_t* b) {
    asm volatile(
        "mma.sync.aligned.m16n8k16.row.col.f32.bf16.bf16.f32 "
        "{%0,%1,%2,%3}, {%4,%5,%6,%7}, {%8,%9}, {%0,%1,%2,%3};"
        : "+f"(c[0]), "+f"(c[1]), "+f"(c[2]), "+f"(c[3])
        : "r"(a[0]), "r"(a[1]), "r"(a[2]), "r"(a[3]), "r"(b[0]), "r"(b[1]));
}

// SMEM tile geometry: rows of 64 bf16 data padded to stride 72 bf16 (144B).
// Fragment LDS word index = r*36 + c  ->  bank (r*4+c)%32, all distinct for
// r in 0..7, c in 0..3: conflict-free fragment loads.
#define AST      72
#define BUF_ELEM (128 * AST)           // bf16 elements per buffer (9216)
#define BUF_W    (BUF_ELEM / 2)        // 32-bit words per buffer   (4608)
#define GEMM_SMEM (4 * BUF_ELEM * 2)   // AH,AL,WH,WL = 73728 bytes

// ---------------------------------------------------------------------------
// HMMA GEMM: C[m,n] = sum_k A[m,k]*W[n,k] + bias[n], 128x128 CTA tile, K=1024.
// 3-term bf16 split: Ah*Wh + Al*Wh + Ah*Wl, fp32 accumulators.
// 8 warps in 2(M)x4(N); each warp owns 64x32 = 4x4 m16n8k16 tiles.
// ---------------------------------------------------------------------------
__device__ __forceinline__ void gemm_tc_body(
    const float* __restrict__ A, const float* __restrict__ W,
    const float* __restrict__ bias, float* __restrict__ C, int remap)
{
    extern __shared__ __nv_bfloat16 smb[];
    uint32_t* smw = (uint32_t*)smb;          // word view, row stride 36 words
    // word-view buffer bases: AH=0, AL=BUF_W, WH=2*BUF_W, WL=3*BUF_W

    const int tid  = threadIdx.x;
    const int lane = tid & 31;
    const int wid  = tid >> 5;
    const int wm   = wid >> 2;               // 0..1 : M half
    const int wn   = wid & 3;                // 0..3 : N quarter
    const int fr   = lane >> 2;              // fragment row 0..7
    const int fc   = lane & 3;               // fragment word col 0..3
    const int m0   = blockIdx.y * 128;
    const int n0   = blockIdx.x * 128;

    float acc[4][4][4];
#pragma unroll
    for (int mt = 0; mt < 4; mt++)
#pragma unroll
        for (int nt = 0; nt < 4; nt++)
#pragma unroll
            for (int i = 0; i < 4; i++) acc[mt][nt][i] = 0.0f;

    for (int chunk = 0; chunk < 16; chunk++) {
        const int k0 = chunk * 64;
        // ---- stage 64 K-cols of A and W as hi/lo bf16 ----
        // 2 tiles x 128 rows x 16 float4 = 4096 float4 over 256 threads
#pragma unroll
        for (int r = 0; r < 16; r++) {
            int idx  = tid + r * 256;
            int tile = idx >> 11;            // 0 = A, 1 = W
            int e    = idx & 2047;
            int row  = e >> 4;
            int kc4  = e & 15;
            const float* src = (tile ? W + (n0 + row) * E_DIM
                                     : A + (m0 + row) * E_DIM) + k0 + kc4 * 4;
            float4 a = *(const float4*)src;
            __nv_bfloat162 h01 = __float22bfloat162_rn(make_float2(a.x, a.y));
            __nv_bfloat162 h23 = __float22bfloat162_rn(make_float2(a.z, a.w));
            float2 f01 = __bfloat1622float2(h01);
            float2 f23 = __bfloat1622float2(h23);
            __nv_bfloat162 l01 = __float22bfloat162_rn(
                make_float2(a.x - f01.x, a.y - f01.y));
            __nv_bfloat162 l23 = __float22bfloat162_rn(
                make_float2(a.z - f23.x, a.w - f23.y));
            __nv_bfloat16* hb = smb + (tile * 2) * BUF_ELEM + row * AST + kc4 * 4;
            *(uint2*)hb             = make_uint2(*(uint32_t*)&h01, *(uint32_t*)&h23);
            *(uint2*)(hb + BUF_ELEM) = make_uint2(*(uint32_t*)&l01, *(uint32_t*)&l23);
        }
        __syncthreads();

        // ---- 4 k16 steps over the staged chunk ----
#pragma unroll
        for (int ks = 0; ks < 4; ks++) {
            uint32_t bh[4][2], bl[4][2];
#pragma unroll
            for (int nt = 0; nt < 4; nt++) {
                int n  = wn * 32 + nt * 8 + fr;
                int wI = n * 36 + ks * 8 + fc;
                bh[nt][0] = smw[2 * BUF_W + wI];
                bh[nt][1] = smw[2 * BUF_W + wI + 4];
                bl[nt][0] = smw[3 * BUF_W + wI];
                bl[nt][1] = smw[3 * BUF_W + wI + 4];
            }
#pragma unroll
            for (int mt = 0; mt < 4; mt++) {
                int r  = wm * 64 + mt * 16 + fr;
                int aI = r * 36 + ks * 8 + fc;
                uint32_t ah[4], al[4];
                ah[0] = smw[aI];
                ah[1] = smw[aI + 8 * 36];
                ah[2] = smw[aI + 4];
                ah[3] = smw[aI + 8 * 36 + 4];
                al[0] = smw[BUF_W + aI];
                al[1] = smw[BUF_W + aI + 8 * 36];
                al[2] = smw[BUF_W + aI + 4];
                al[3] = smw[BUF_W + aI + 8 * 36 + 4];
#pragma unroll
                for (int nt = 0; nt < 4; nt++) {
                    mma_bf16(acc[mt][nt], ah, bh[nt]);
                    mma_bf16(acc[mt][nt], al, bh[nt]);
                    mma_bf16(acc[mt][nt], ah, bl[nt]);
                }
            }
        }
        __syncthreads();
    }

    // ---- epilogue: registers -> gmem with bias (+ optional BHSD remap) ----
#pragma unroll
    for (int nt = 0; nt < 4; nt++) {
        int ncol = n0 + wn * 32 + nt * 8 + fc * 2;
        float bx = bias[ncol];
        float by = bias[ncol + 1];
#pragma unroll
        for (int mt = 0; mt < 4; mt++) {
            int mrow = m0 + wm * 64 + mt * 16 + fr;
            float* acc4 = acc[mt][nt];
#pragma unroll
            for (int half = 0; half < 2; half++) {
                int m = mrow + half * 8;
                float2 v = make_float2(acc4[half * 2 + 0] + bx,
                                       acc4[half * 2 + 1] + by);
                float* dst;
                if (remap) {
                    int b_ = m >> 11, s = m & (SEQ_LEN - 1);
                    int h = ncol >> 6, d = ncol & 63;
                    dst = C + (((size_t)(b_ * N_HEADS + h) * SEQ_LEN + s) * H_DIM) + d;
                } else {
                    dst = C + (size_t)m * E_DIM + ncol;
                }
                *(float2*)dst = v;
            }
        }
    }
}

__global__ __launch_bounds__(256, 2)
void qkv_tc_kernel(const float* __restrict__ x,
                   const float* __restrict__ wq, const float* __restrict__ bq,
                   const float* __restrict__ wk, const float* __restrict__ bk,
                   const float* __restrict__ wv, const float* __restrict__ bv)
{
    const float* W; const float* bias; float* C;
    if (blockIdx.z == 0)      { W = wq; bias = bq; C = g_Q; }
    else if (blockIdx.z == 1) { W = wk; bias = bk; C = g_K; }
    else                      { W = wv; bias = bv; C = g_V; }
    gemm_tc_body(x, W, bias, C, 1);
}

__global__ __launch_bounds__(256, 2)
void out_tc_kernel(const float* __restrict__ wo, const float* __restrict__ bo,
                   float* __restrict__ out)
{
    gemm_tc_body(g_attn, wo, bo, out, 0);
}

// ---------------------------------------------------------------------------
// Flash attention (byte-identical to the verified R1 kernel)
// ---------------------------------------------------------------------------
#define FL_SMEM_BYTES (4 * 64 * 68 * 4)

__global__ __launch_bounds__(256)
void flash_kernel()
{
    extern __shared__ float smf[];
    float* Qs = smf;
    float* Ks = smf + 64 * 68;
    float* Vs = smf + 2 * 64 * 68;
    float* Ps = smf + 3 * 64 * 68;

    const int tid = threadIdx.x;
    const int ty = tid >> 4;
    const int tx = tid & 15;
    const int bh = blockIdx.y;
    const int q0 = blockIdx.x * 64;

    const float* Qp = g_Q + (size_t)bh * SEQ_LEN * H_DIM;
    const float* Kp = g_K + (size_t)bh * SEQ_LEN * H_DIM;
    const float* Vp = g_V + (size_t)bh * SEQ_LEN * H_DIM;

#pragma unroll
    for (int t = 0; t < 16; t++) {
        int idx = tid + t * 256;
        int r = idx >> 6, d = idx & 63;
        Qs[d * 68 + r] = Qp[(size_t)(q0 + r) * H_DIM + d] * 0.125f;
    }

    float m_i[4], l_i[4], o[4][4];
#pragma unroll
    for (int i = 0; i < 4; i++) {
        m_i[i] = -1e30f; l_i[i] = 0.0f;
#pragma unroll
        for (int j = 0; j < 4; j++) o[i][j] = 0.0f;
    }
    __syncthreads();

    for (int kt = 0; kt < SEQ_LEN; kt += 64) {
#pragma unroll
        for (int t = 0; t < 16; t++) {
            int idx = tid + t * 256;
            int r = idx >> 6, d = idx & 63;
            Ks[d * 68 + r] = Kp[(size_t)(kt + r) * H_DIM + d];
            Vs[r * 68 + d] = Vp[(size_t)(kt + r) * H_DIM + d];
        }
        __syncthreads();

        float s4[4][4];
#pragma unroll
        for (int i = 0; i < 4; i++)
#pragma unroll
            for (int j = 0; j < 4; j++) s4[i][j] = 0.0f;

#pragma unroll 8
        for (int d = 0; d < 64; d++) {
            float4 a4 = *(const float4*)&Qs[d * 68 + ty * 4];
            float4 b4 = *(const float4*)&Ks[d * 68 + tx * 4];
            float av[4] = {a4.x, a4.y, a4.z, a4.w};
            float bv[4] = {b4.x, b4.y, b4.z, b4.w};
#pragma unroll
            for (int i = 0; i < 4; i++)
#pragma unroll
                for (int j = 0; j < 4; j++)
                    s4[i][j] = fmaf(av[i], bv[j], s4[i][j]);
        }

#pragma unroll
        for (int i = 0; i < 4; i++) {
            float mx = fmaxf(fmaxf(s4[i][0], s4[i][1]), fmaxf(s4[i][2], s4[i][3]));
#pragma unroll
            for (int off = 8; off >= 1; off >>= 1)
                mx = fmaxf(mx, __shfl_xor_sync(0xffffffffu, mx, off));
            float mn = fmaxf(m_i[i], mx);
            float corr = __expf(m_i[i] - mn);
            m_i[i] = mn;
            float p[4], rs = 0.0f;
#pragma unroll
            for (int j = 0; j < 4; j++) {
                p[j] = __expf(s4[i][j] - mn);
                rs += p[j];
            }
#pragma unroll
            for (int off = 8; off >= 1; off >>= 1)
                rs += __shfl_xor_sync(0xffffffffu, rs, off);
            l_i[i] = l_i[i] * corr + rs;
#pragma unroll
            for (int j = 0; j < 4; j++) o[i][j] *= corr;
#pragma unroll
            for (int j = 0; j < 4; j++)
                Ps[(tx * 4 + j) * 68 + ty * 4 + i] = p[j];
        }
        __syncthreads();

#pragma unroll 8
        for (int j = 0; j < 64; j++) {
            float4 p4 = *(const float4*)&Ps[j * 68 + ty * 4];
            float4 v4 = *(const float4*)&Vs[j * 68 + tx * 4];
            float pv[4] = {p4.x, p4.y, p4.z, p4.w};
            float vv[4] = {v4.x, v4.y, v4.z, v4.w};
#pragma unroll
            for (int i = 0; i < 4; i++)
#pragma unroll
                for (int jj = 0; jj < 4; jj++)
                    o[i][jj] = fmaf(pv[i], vv[jj], o[i][jj]);
        }
        __syncthreads();
    }

    const int b_ = bh >> 4;
    const int h  = bh & 15;
#pragma unroll
    for (int i = 0; i < 4; i++) {
        float inv = 1.0f / l_i[i];
        int srow = q0 + ty * 4 + i;
        float* dst = g_attn + (size_t)(b_ * SEQ_LEN + srow) * E_DIM + h * H_DIM + tx * 4;
        *(float4*)dst = make_float4(o[i][0] * inv, o[i][1] * inv,
                                    o[i][2] * inv, o[i][3] * inv);
    }
}

// ---------------------------------------------------------------------------
extern "C" void kernel_launch(void* const* d_in, const int* in_sizes, int n_in,
                              void* d_out, int out_size)
{
    const float* x  = (const float*)d_in[0];
    const float* wq = (const float*)d_in[1];
    const float* bq = (const float*)d_in[2];
    const float* wk = (const float*)d_in[3];
    const float* bk = (const float*)d_in[4];
    const float* wv = (const float*)d_in[5];
    const float* bv = (const float*)d_in[6];
    const float* wo = (const float*)d_in[7];
    const float* bo = (const float*)d_in[8];
    float* out = (float*)d_out;

    cudaFuncSetAttribute(qkv_tc_kernel,
                         cudaFuncAttributeMaxDynamicSharedMemorySize, GEMM_SMEM);
    cudaFuncSetAttribute(out_tc_kernel,
                         cudaFuncAttributeMaxDynamicSharedMemorySize, GEMM_SMEM);
    cudaFuncSetAttribute(flash_kernel,
                         cudaFuncAttributeMaxDynamicSharedMemorySize, FL_SMEM_BYTES);

    dim3 gqkv(E_DIM / 128, M_TOT / 128, 3);
    qkv_tc_kernel<<<gqkv, 256, GEMM_SMEM>>>(x, wq, bq, wk, bk, wv, bv);

    dim3 gfl(SEQ_LEN / 64, N_BATCH * N_HEADS);
    flash_kernel<<<gfl, 256, FL_SMEM_BYTES>>>();

    dim3 gout(E_DIM / 128, M_TOT / 128);
    out_tc_kernel<<<gout, 256, GEMM_SMEM>>>(wo, bo, out);
}

// round 13
// speedup vs baseline: 2.0155x; 1.4918x over previous
#include <cuda_runtime.h>
#include <cuda_bf16.h>
#include <cstdint>

#define E_DIM   1024
#define N_HEADS 16
#define H_DIM   64
#define N_BATCH 2
#define SEQ_LEN 2048
#define M_TOT   (N_BATCH * SEQ_LEN)   // 4096

__device__ float g_Q[N_BATCH * N_HEADS * SEQ_LEN * H_DIM];
__device__ float g_K[N_BATCH * N_HEADS * SEQ_LEN * H_DIM];
__device__ float g_V[N_BATCH * N_HEADS * SEQ_LEN * H_DIM];
__device__ float g_attn[M_TOT * E_DIM];

// ---------------------------------------------------------------------------
// HMMA m16n8k16 bf16 (sm_80+ baseline PTX; legal on plain sm_103 target)
// ---------------------------------------------------------------------------
__device__ __forceinline__ void mma_bf16(float* c, const uint32_t* a,
                                         const uint32_t* b) {
    asm volatile(
        "mma.sync.aligned.m16n8k16.row.col.f32.bf16.bf16.f32 "
        "{%0,%1,%2,%3}, {%4,%5,%6,%7}, {%8,%9}, {%0,%1,%2,%3};"
        : "+f"(c[0]), "+f"(c[1]), "+f"(c[2]), "+f"(c[3])
        : "r"(a[0]), "r"(a[1]), "r"(a[2]), "r"(a[3]), "r"(b[0]), "r"(b[1]));
}

// Fast exp on FMA/ALU pipes (no MUFU). |rel err| ~3e-6 for x <= 0.
__device__ __forceinline__ float fast_exp(float x) {
    float t = fmaxf(x * 1.44269504089f, -125.0f);
    float u = t + 12582912.0f;              // RN to integer in mantissa
    int   iu = __float_as_int(u);
    float fi = u - 12582912.0f;
    float f  = t - fi;                      // f in [-0.5, 0.5]
    float p  = 1.3333558e-3f;               // Taylor for 2^f
    p = fmaf(p, f, 9.6181291e-3f);
    p = fmaf(p, f, 5.5504109e-2f);
    p = fmaf(p, f, 2.4022647e-1f);
    p = fmaf(p, f, 6.9314720e-1f);
    p = fmaf(p, f, 1.0f);
    float sc = __int_as_float((iu - 0x4B400000 + 127) << 23);
    return p * sc;
}

// ===========================================================================
// HMMA GEMM (byte-identical to verified R8 kernel)
// ===========================================================================
#define AST      72
#define BUF_ELEM (128 * AST)
#define BUF_W    (BUF_ELEM / 2)
#define GEMM_SMEM (4 * BUF_ELEM * 2)

__device__ __forceinline__ void gemm_tc_body(
    const float* __restrict__ A, const float* __restrict__ W,
    const float* __restrict__ bias, float* __restrict__ C, int remap)
{
    extern __shared__ __nv_bfloat16 smb[];
    uint32_t* smw = (uint32_t*)smb;

    const int tid  = threadIdx.x;
    const int lane = tid & 31;
    const int wid  = tid >> 5;
    const int wm   = wid >> 2;
    const int wn   = wid & 3;
    const int fr   = lane >> 2;
    const int fc   = lane & 3;
    const int m0   = blockIdx.y * 128;
    const int n0   = blockIdx.x * 128;

    float acc[4][4][4];
#pragma unroll
    for (int mt = 0; mt < 4; mt++)
#pragma unroll
        for (int nt = 0; nt < 4; nt++)
#pragma unroll
            for (int i = 0; i < 4; i++) acc[mt][nt][i] = 0.0f;

    for (int chunk = 0; chunk < 16; chunk++) {
        const int k0 = chunk * 64;
#pragma unroll
        for (int r = 0; r < 16; r++) {
            int idx  = tid + r * 256;
            int tile = idx >> 11;
            int e    = idx & 2047;
            int row  = e >> 4;
            int kc4  = e & 15;
            const float* src = (tile ? W + (n0 + row) * E_DIM
                                     : A + (m0 + row) * E_DIM) + k0 + kc4 * 4;
            float4 a = *(const float4*)src;
            __nv_bfloat162 h01 = __float22bfloat162_rn(make_float2(a.x, a.y));
            __nv_bfloat162 h23 = __float22bfloat162_rn(make_float2(a.z, a.w));
            float2 f01 = __bfloat1622float2(h01);
            float2 f23 = __bfloat1622float2(h23);
            __nv_bfloat162 l01 = __float22bfloat162_rn(
                make_float2(a.x - f01.x, a.y - f01.y));
            __nv_bfloat162 l23 = __float22bfloat162_rn(
                make_float2(a.z - f23.x, a.w - f23.y));
            __nv_bfloat16* hb = smb + (tile * 2) * BUF_ELEM + row * AST + kc4 * 4;
            *(uint2*)hb              = make_uint2(*(uint32_t*)&h01, *(uint32_t*)&h23);
            *(uint2*)(hb + BUF_ELEM) = make_uint2(*(uint32_t*)&l01, *(uint32_t*)&l23);
        }
        __syncthreads();

#pragma unroll
        for (int ks = 0; ks < 4; ks++) {
            uint32_t bh[4][2], bl[4][2];
#pragma unroll
            for (int nt = 0; nt < 4; nt++) {
                int n  = wn * 32 + nt * 8 + fr;
                int wI = n * 36 + ks * 8 + fc;
                bh[nt][0] = smw[2 * BUF_W + wI];
                bh[nt][1] = smw[2 * BUF_W + wI + 4];
                bl[nt][0] = smw[3 * BUF_W + wI];
                bl[nt][1] = smw[3 * BUF_W + wI + 4];
            }
#pragma unroll
            for (int mt = 0; mt < 4; mt++) {
                int r  = wm * 64 + mt * 16 + fr;
                int aI = r * 36 + ks * 8 + fc;
                uint32_t ah[4], al[4];
                ah[0] = smw[aI];
                ah[1] = smw[aI + 8 * 36];
                ah[2] = smw[aI + 4];
                ah[3] = smw[aI + 8 * 36 + 4];
                al[0] = smw[BUF_W + aI];
                al[1] = smw[BUF_W + aI + 8 * 36];
                al[2] = smw[BUF_W + aI + 4];
                al[3] = smw[BUF_W + aI + 8 * 36 + 4];
#pragma unroll
                for (int nt = 0; nt < 4; nt++) {
                    mma_bf16(acc[mt][nt], ah, bh[nt]);
                    mma_bf16(acc[mt][nt], al, bh[nt]);
                    mma_bf16(acc[mt][nt], ah, bl[nt]);
                }
            }
        }
        __syncthreads();
    }

#pragma unroll
    for (int nt = 0; nt < 4; nt++) {
        int ncol = n0 + wn * 32 + nt * 8 + fc * 2;
        float bx = bias[ncol];
        float by = bias[ncol + 1];
#pragma unroll
        for (int mt = 0; mt < 4; mt++) {
            int mrow = m0 + wm * 64 + mt * 16 + fr;
            float* acc4 = acc[mt][nt];
#pragma unroll
            for (int half = 0; half < 2; half++) {
                int m = mrow + half * 8;
                float2 v = make_float2(acc4[half * 2 + 0] + bx,
                                       acc4[half * 2 + 1] + by);
                float* dst;
                if (remap) {
                    int b_ = m >> 11, s = m & (SEQ_LEN - 1);
                    int h = ncol >> 6, d = ncol & 63;
                    dst = C + (((size_t)(b_ * N_HEADS + h) * SEQ_LEN + s) * H_DIM) + d;
                } else {
                    dst = C + (size_t)m * E_DIM + ncol;
                }
                *(float2*)dst = v;
            }
        }
    }
}

__global__ __launch_bounds__(256, 2)
void qkv_tc_kernel(const float* __restrict__ x,
                   const float* __restrict__ wq, const float* __restrict__ bq,
                   const float* __restrict__ wk, const float* __restrict__ bk,
                   const float* __restrict__ wv, const float* __restrict__ bv)
{
    const float* W; const float* bias; float* C;
    if (blockIdx.z == 0)      { W = wq; bias = bq; C = g_Q; }
    else if (blockIdx.z == 1) { W = wk; bias = bk; C = g_K; }
    else                      { W = wv; bias = bv; C = g_V; }
    gemm_tc_body(x, W, bias, C, 1);
}

__global__ __launch_bounds__(256, 2)
void out_tc_kernel(const float* __restrict__ wo, const float* __restrict__ bo,
                   float* __restrict__ out)
{
    gemm_tc_body(g_attn, wo, bo, out, 0);
}

// ===========================================================================
// HMMA flash attention.
// One CTA per (bh, 128-row q-block), 8 warps, each warp owns 16 q-rows.
// smem (bf16 elems): QH 0, QL 9216, KH 18432, KL 27648, VHT 36864, VLT 45568.
// Q/K: row-major [pos][d], stride 72.  V: transposed [d][pos], stride 136.
// ===========================================================================
#define FQ_H   0
#define FQ_L   9216
#define FK_H   18432
#define FK_L   27648
#define FV_H   36864
#define FV_L   45568
#define FL_SMEM_BYTES ((45568 + 64 * 136) * 2)   // 108544 bytes

__global__ __launch_bounds__(256)
void flash_tc_kernel()
{
    extern __shared__ __nv_bfloat16 smb[];
    uint32_t* smw = (uint32_t*)smb;
    // word-view bases
    const int WQ_H = 0,    WQ_L = 4608;
    const int WK_H = 9216, WK_L = 13824;
    const int WV_H = 18432, WV_L = 22784;

    const int tid  = threadIdx.x;
    const int lane = tid & 31;
    const int wid  = tid >> 5;
    const int fr   = lane >> 2;     // 0..7
    const int fc   = lane & 3;      // 0..3
    const int bh   = blockIdx.y;
    const int q0   = blockIdx.x * 128;

    const float* Qp = g_Q + (size_t)bh * SEQ_LEN * H_DIM;
    const float* Kp = g_K + (size_t)bh * SEQ_LEN * H_DIM;
    const float* Vp = g_V + (size_t)bh * SEQ_LEN * H_DIM;

    // ---- stage Q block (fold 1/sqrt(64) = 0.125), hi/lo split ----
#pragma unroll
    for (int r = 0; r < 8; r++) {
        int idx = tid + r * 256;          // 0..2047 float4s
        int row = idx >> 4;
        int kc4 = idx & 15;
        float4 a = *(const float4*)(Qp + (size_t)(q0 + row) * H_DIM + kc4 * 4);
        a.x *= 0.125f; a.y *= 0.125f; a.z *= 0.125f; a.w *= 0.125f;
        __nv_bfloat162 h01 = __float22bfloat162_rn(make_float2(a.x, a.y));
        __nv_bfloat162 h23 = __float22bfloat162_rn(make_float2(a.z, a.w));
        float2 f01 = __bfloat1622float2(h01);
        float2 f23 = __bfloat1622float2(h23);
        __nv_bfloat162 l01 = __float22bfloat162_rn(make_float2(a.x - f01.x, a.y - f01.y));
        __nv_bfloat162 l23 = __float22bfloat162_rn(make_float2(a.z - f23.x, a.w - f23.y));
        __nv_bfloat16* dst = smb + FQ_H + row * AST + kc4 * 4;
        *(uint2*)dst            = make_uint2(*(uint32_t*)&h01, *(uint32_t*)&h23);
        *(uint2*)(dst + FQ_L)   = make_uint2(*(uint32_t*)&l01, *(uint32_t*)&l23);
    }

    float m0r = -1e30f, m1r = -1e30f, l0r = 0.0f, l1r = 0.0f;
    float oacc[8][4];
#pragma unroll
    for (int nt = 0; nt < 8; nt++)
#pragma unroll
        for (int i = 0; i < 4; i++) oacc[nt][i] = 0.0f;

    __syncthreads();

    for (int kt = 0; kt < SEQ_LEN; kt += 128) {
        // ---- stage K (row-major hi/lo) and V (transposed hi/lo) ----
#pragma unroll
        for (int r = 0; r < 8; r++) {
            int idx = tid + r * 256;
            int row = idx >> 4;
            int kc4 = idx & 15;
            float4 a = *(const float4*)(Kp + (size_t)(kt + row) * H_DIM + kc4 * 4);
            __nv_bfloat162 h01 = __float22bfloat162_rn(make_float2(a.x, a.y));
            __nv_bfloat162 h23 = __float22bfloat162_rn(make_float2(a.z, a.w));
            float2 f01 = __bfloat1622float2(h01);
            float2 f23 = __bfloat1622float2(h23);
            __nv_bfloat162 l01 = __float22bfloat162_rn(make_float2(a.x - f01.x, a.y - f01.y));
            __nv_bfloat162 l23 = __float22bfloat162_rn(make_float2(a.z - f23.x, a.w - f23.y));
            __nv_bfloat16* dst = smb + FK_H + row * AST + kc4 * 4;
            *(uint2*)dst          = make_uint2(*(uint32_t*)&h01, *(uint32_t*)&h23);
            *(uint2*)(dst + BUF_ELEM) = make_uint2(*(uint32_t*)&l01, *(uint32_t*)&l23);

            float4 v = *(const float4*)(Vp + (size_t)(kt + row) * H_DIM + kc4 * 4);
            float vv[4] = {v.x, v.y, v.z, v.w};
#pragma unroll
            for (int j = 0; j < 4; j++) {
                int d = kc4 * 4 + j;
                __nv_bfloat16 hv = __float2bfloat16_rn(vv[j]);
                float lvf = vv[j] - __bfloat162float(hv);
                smb[FV_H + d * 136 + row] = hv;
                smb[FV_L + d * 136 + row] = __float2bfloat16_rn(lvf);
            }
        }
        __syncthreads();

        // ---- S = Q * K^T (3-term split), warp rows wid*16..+15 ----
        float sacc[16][4];
#pragma unroll
        for (int nt = 0; nt < 16; nt++)
#pragma unroll
            for (int i = 0; i < 4; i++) sacc[nt][i] = 0.0f;

#pragma unroll
        for (int ks = 0; ks < 4; ks++) {
            int aI = (wid * 16 + fr) * 36 + ks * 8 + fc;
            uint32_t ah[4], al[4];
            ah[0] = smw[WQ_H + aI];
            ah[1] = smw[WQ_H + aI + 8 * 36];
            ah[2] = smw[WQ_H + aI + 4];
            ah[3] = smw[WQ_H + aI + 8 * 36 + 4];
            al[0] = smw[WQ_L + aI];
            al[1] = smw[WQ_L + aI + 8 * 36];
            al[2] = smw[WQ_L + aI + 4];
            al[3] = smw[WQ_L + aI + 8 * 36 + 4];
#pragma unroll
            for (int nt = 0; nt < 16; nt++) {
                int wI = (nt * 8 + fr) * 36 + ks * 8 + fc;
                uint32_t bh[2], bl[2];
                bh[0] = smw[WK_H + wI]; bh[1] = smw[WK_H + wI + 4];
                bl[0] = smw[WK_L + wI]; bl[1] = smw[WK_L + wI + 4];
                mma_bf16(sacc[nt], ah, bh);
                mma_bf16(sacc[nt], al, bh);
                mma_bf16(sacc[nt], ah, bl);
            }
        }

        // ---- online softmax (rows fr and fr+8 of warp tile) ----
        float mx0 = -1e30f, mx1 = -1e30f;
#pragma unroll
        for (int nt = 0; nt < 16; nt++) {
            mx0 = fmaxf(mx0, fmaxf(sacc[nt][0], sacc[nt][1]));
            mx1 = fmaxf(mx1, fmaxf(sacc[nt][2], sacc[nt][3]));
        }
#pragma unroll
        for (int off = 1; off <= 2; off <<= 1) {
            mx0 = fmaxf(mx0, __shfl_xor_sync(0xffffffffu, mx0, off));
            mx1 = fmaxf(mx1, __shfl_xor_sync(0xffffffffu, mx1, off));
        }
        float mn0 = fmaxf(m0r, mx0), mn1 = fmaxf(m1r, mx1);
        float corr0 = fast_exp(m0r - mn0), corr1 = fast_exp(m1r - mn1);
        m0r = mn0; m1r = mn1;

        float sum0 = 0.0f, sum1 = 0.0f;
#pragma unroll
        for (int nt = 0; nt < 16; nt++) {
            float p0 = fast_exp(sacc[nt][0] - m0r);
            float p1 = fast_exp(sacc[nt][1] - m0r);
            float p2 = fast_exp(sacc[nt][2] - m1r);
            float p3 = fast_exp(sacc[nt][3] - m1r);
            sacc[nt][0] = p0; sacc[nt][1] = p1;
            sacc[nt][2] = p2; sacc[nt][3] = p3;
            sum0 += p0 + p1; sum1 += p2 + p3;
        }
#pragma unroll
        for (int off = 1; off <= 2; off <<= 1) {
            sum0 += __shfl_xor_sync(0xffffffffu, sum0, off);
            sum1 += __shfl_xor_sync(0xffffffffu, sum1, off);
        }
        l0r = l0r * corr0 + sum0;
        l1r = l1r * corr1 + sum1;

#pragma unroll
        for (int nt = 0; nt < 8; nt++) {
            oacc[nt][0] *= corr0; oacc[nt][1] *= corr0;
            oacc[nt][2] *= corr1; oacc[nt][3] *= corr1;
        }

        // ---- O += P * V (3-term split; P from registers) ----
#pragma unroll
        for (int ks = 0; ks < 8; ks++) {
            uint32_t ph[4], pl[4];
            {
                float* t0 = sacc[2 * ks];
                float* t1 = sacc[2 * ks + 1];
                __nv_bfloat162 h;
                float2 bf;
                h = __float22bfloat162_rn(make_float2(t0[0], t0[1]));
                ph[0] = *(uint32_t*)&h; bf = __bfloat1622float2(h);
                h = __float22bfloat162_rn(make_float2(t0[0] - bf.x, t0[1] - bf.y));
                pl[0] = *(uint32_t*)&h;
                h = __float22bfloat162_rn(make_float2(t0[2], t0[3]));
                ph[1] = *(uint32_t*)&h; bf = __bfloat1622float2(h);
                h = __float22bfloat162_rn(make_float2(t0[2] - bf.x, t0[3] - bf.y));
                pl[1] = *(uint32_t*)&h;
                h = __float22bfloat162_rn(make_float2(t1[0], t1[1]));
                ph[2] = *(uint32_t*)&h; bf = __bfloat1622float2(h);
                h = __float22bfloat162_rn(make_float2(t1[0] - bf.x, t1[1] - bf.y));
                pl[2] = *(uint32_t*)&h;
                h = __float22bfloat162_rn(make_float2(t1[2], t1[3]));
                ph[3] = *(uint32_t*)&h; bf = __bfloat1622float2(h);
                h = __float22bfloat162_rn(make_float2(t1[2] - bf.x, t1[3] - bf.y));
                pl[3] = *(uint32_t*)&h;
            }
#pragma unroll
            for (int nt = 0; nt < 8; nt++) {
                int wI = (nt * 8 + fr) * 68 + ks * 8 + fc;
                uint32_t bh[2], bl[2];
                bh[0] = smw[WV_H + wI]; bh[1] = smw[WV_H + wI + 4];
                bl[0] = smw[WV_L + wI]; bl[1] = smw[WV_L + wI + 4];
                mma_bf16(oacc[nt], ph, bh);
                mma_bf16(oacc[nt], pl, bh);
                mma_bf16(oacc[nt], ph, bl);
            }
        }
        __syncthreads();
    }

    // ---- write O/l into [B,S,E] ----
    const int b_ = bh >> 4;
    const int h  = bh & 15;
    float inv0 = 1.0f / l0r, inv1 = 1.0f / l1r;
    int row0 = q0 + wid * 16 + fr;
#pragma unroll
    for (int nt = 0; nt < 8; nt++) {
        int col = h * H_DIM + nt * 8 + fc * 2;
        float* d0 = g_attn + (size_t)(b_ * SEQ_LEN + row0) * E_DIM + col;
        float* d1 = g_attn + (size_t)(b_ * SEQ_LEN + row0 + 8) * E_DIM + col;
        *(float2*)d0 = make_float2(oacc[nt][0] * inv0, oacc[nt][1] * inv0);
        *(float2*)d1 = make_float2(oacc[nt][2] * inv1, oacc[nt][3] * inv1);
    }
}

// ---------------------------------------------------------------------------
extern "C" void kernel_launch(void* const* d_in, const int* in_sizes, int n_in,
                              void* d_out, int out_size)
{
    const float* x  = (const float*)d_in[0];
    const float* wq = (const float*)d_in[1];
    const float* bq = (const float*)d_in[2];
    const float* wk = (const float*)d_in[3];
    const float* bk = (const float*)d_in[4];
    const float* wv = (const float*)d_in[5];
    const float* bv = (const float*)d_in[6];
    const float* wo = (const float*)d_in[7];
    const float* bo = (const float*)d_in[8];
    float* out = (float*)d_out;

    cudaFuncSetAttribute(qkv_tc_kernel,
                         cudaFuncAttributeMaxDynamicSharedMemorySize, GEMM_SMEM);
    cudaFuncSetAttribute(out_tc_kernel,
                         cudaFuncAttributeMaxDynamicSharedMemorySize, GEMM_SMEM);
    cudaFuncSetAttribute(flash_tc_kernel,
                         cudaFuncAttributeMaxDynamicSharedMemorySize, FL_SMEM_BYTES);

    dim3 gqkv(E_DIM / 128, M_TOT / 128, 3);
    qkv_tc_kernel<<<gqkv, 256, GEMM_SMEM>>>(x, wq, bq, wk, bk, wv, bv);

    dim3 gfl(SEQ_LEN / 128, N_BATCH * N_HEADS);
    flash_tc_kernel<<<gfl, 256, FL_SMEM_BYTES>>>();

    dim3 gout(E_DIM / 128, M_TOT / 128);
    out_tc_kernel<<<gout, 256, GEMM_SMEM>>>(wo, bo, out);
}

// round 14
// speedup vs baseline: 2.1817x; 1.0825x over previous
#include <cuda_runtime.h>
#include <cuda_bf16.h>
#include <cstdint>

#define E_DIM   1024
#define N_HEADS 16
#define H_DIM   64
#define N_BATCH 2
#define SEQ_LEN 2048
#define M_TOT   (N_BATCH * SEQ_LEN)   // 4096

__device__ float g_Q[N_BATCH * N_HEADS * SEQ_LEN * H_DIM];
__device__ float g_K[N_BATCH * N_HEADS * SEQ_LEN * H_DIM];
__device__ float g_V[N_BATCH * N_HEADS * SEQ_LEN * H_DIM];
__device__ float g_attn[M_TOT * E_DIM];

// ---------------------------------------------------------------------------
// HMMA m16n8k16 bf16 (sm_80+ baseline PTX; legal on plain sm_103 target)
// ---------------------------------------------------------------------------
__device__ __forceinline__ void mma_bf16(float* c, const uint32_t* a,
                                         const uint32_t* b) {
    asm volatile(
        "mma.sync.aligned.m16n8k16.row.col.f32.bf16.bf16.f32 "
        "{%0,%1,%2,%3}, {%4,%5,%6,%7}, {%8,%9}, {%0,%1,%2,%3};"
        : "+f"(c[0]), "+f"(c[1]), "+f"(c[2]), "+f"(c[3])
        : "r"(a[0]), "r"(a[1]), "r"(a[2]), "r"(a[3]), "r"(b[0]), "r"(b[1]));
}

// Fast exp on FMA/ALU pipes (no MUFU). |rel err| ~3e-6 for x <= 0.
__device__ __forceinline__ float fast_exp(float x) {
    float t = fmaxf(x * 1.44269504089f, -125.0f);
    float u = t + 12582912.0f;              // RN to integer in mantissa
    int   iu = __float_as_int(u);
    float fi = u - 12582912.0f;
    float f  = t - fi;                      // f in [-0.5, 0.5]
    float p  = 1.3333558e-3f;               // Taylor for 2^f
    p = fmaf(p, f, 9.6181291e-3f);
    p = fmaf(p, f, 5.5504109e-2f);
    p = fmaf(p, f, 2.4022647e-1f);
    p = fmaf(p, f, 6.9314720e-1f);
    p = fmaf(p, f, 1.0f);
    float sc = __int_as_float((iu - 0x4B400000 + 127) << 23);
    return p * sc;
}

// Split one float4 into hi/lo bf16x2 pairs.
__device__ __forceinline__ void split_f4(float4 a, uint2& hi, uint2& lo) {
    __nv_bfloat162 h01 = __float22bfloat162_rn(make_float2(a.x, a.y));
    __nv_bfloat162 h23 = __float22bfloat162_rn(make_float2(a.z, a.w));
    float2 f01 = __bfloat1622float2(h01);
    float2 f23 = __bfloat1622float2(h23);
    __nv_bfloat162 l01 = __float22bfloat162_rn(make_float2(a.x - f01.x, a.y - f01.y));
    __nv_bfloat162 l23 = __float22bfloat162_rn(make_float2(a.z - f23.x, a.w - f23.y));
    hi = make_uint2(*(uint32_t*)&h01, *(uint32_t*)&h23);
    lo = make_uint2(*(uint32_t*)&l01, *(uint32_t*)&l23);
}

// ===========================================================================
// HMMA GEMM (byte-identical logic to verified R8 kernel)
// ===========================================================================
#define AST      72
#define BUF_ELEM (128 * AST)
#define BUF_W    (BUF_ELEM / 2)
#define GEMM_SMEM (4 * BUF_ELEM * 2)

__device__ __forceinline__ void gemm_tc_body(
    const float* __restrict__ A, const float* __restrict__ W,
    const float* __restrict__ bias, float* __restrict__ C, int remap)
{
    extern __shared__ __nv_bfloat16 smb[];
    uint32_t* smw = (uint32_t*)smb;

    const int tid  = threadIdx.x;
    const int lane = tid & 31;
    const int wid  = tid >> 5;
    const int wm   = wid >> 2;
    const int wn   = wid & 3;
    const int fr   = lane >> 2;
    const int fc   = lane & 3;
    const int m0   = blockIdx.y * 128;
    const int n0   = blockIdx.x * 128;

    float acc[4][4][4];
#pragma unroll
    for (int mt = 0; mt < 4; mt++)
#pragma unroll
        for (int nt = 0; nt < 4; nt++)
#pragma unroll
            for (int i = 0; i < 4; i++) acc[mt][nt][i] = 0.0f;

    for (int chunk = 0; chunk < 16; chunk++) {
        const int k0 = chunk * 64;
#pragma unroll
        for (int r = 0; r < 16; r++) {
            int idx  = tid + r * 256;
            int tile = idx >> 11;
            int e    = idx & 2047;
            int row  = e >> 4;
            int kc4  = e & 15;
            const float* src = (tile ? W + (n0 + row) * E_DIM
                                     : A + (m0 + row) * E_DIM) + k0 + kc4 * 4;
            float4 a = *(const float4*)src;
            uint2 hi, lo;
            split_f4(a, hi, lo);
            __nv_bfloat16* hb = smb + (tile * 2) * BUF_ELEM + row * AST + kc4 * 4;
            *(uint2*)hb              = hi;
            *(uint2*)(hb + BUF_ELEM) = lo;
        }
        __syncthreads();

#pragma unroll
        for (int ks = 0; ks < 4; ks++) {
            uint32_t bh[4][2], bl[4][2];
#pragma unroll
            for (int nt = 0; nt < 4; nt++) {
                int n  = wn * 32 + nt * 8 + fr;
                int wI = n * 36 + ks * 8 + fc;
                bh[nt][0] = smw[2 * BUF_W + wI];
                bh[nt][1] = smw[2 * BUF_W + wI + 4];
                bl[nt][0] = smw[3 * BUF_W + wI];
                bl[nt][1] = smw[3 * BUF_W + wI + 4];
            }
#pragma unroll
            for (int mt = 0; mt < 4; mt++) {
                int r  = wm * 64 + mt * 16 + fr;
                int aI = r * 36 + ks * 8 + fc;
                uint32_t ah[4], al[4];
                ah[0] = smw[aI];
                ah[1] = smw[aI + 8 * 36];
                ah[2] = smw[aI + 4];
                ah[3] = smw[aI + 8 * 36 + 4];
                al[0] = smw[BUF_W + aI];
                al[1] = smw[BUF_W + aI + 8 * 36];
                al[2] = smw[BUF_W + aI + 4];
                al[3] = smw[BUF_W + aI + 8 * 36 + 4];
#pragma unroll
                for (int nt = 0; nt < 4; nt++) {
                    mma_bf16(acc[mt][nt], ah, bh[nt]);
                    mma_bf16(acc[mt][nt], al, bh[nt]);
                    mma_bf16(acc[mt][nt], ah, bl[nt]);
                }
            }
        }
        __syncthreads();
    }

#pragma unroll
    for (int nt = 0; nt < 4; nt++) {
        int ncol = n0 + wn * 32 + nt * 8 + fc * 2;
        float bx = bias[ncol];
        float by = bias[ncol + 1];
#pragma unroll
        for (int mt = 0; mt < 4; mt++) {
            int mrow = m0 + wm * 64 + mt * 16 + fr;
            float* acc4 = acc[mt][nt];
#pragma unroll
            for (int half = 0; half < 2; half++) {
                int m = mrow + half * 8;
                float2 v = make_float2(acc4[half * 2 + 0] + bx,
                                       acc4[half * 2 + 1] + by);
                float* dst;
                if (remap) {
                    int b_ = m >> 11, s = m & (SEQ_LEN - 1);
                    int h = ncol >> 6, d = ncol & 63;
                    dst = C + (((size_t)(b_ * N_HEADS + h) * SEQ_LEN + s) * H_DIM) + d;
                } else {
                    dst = C + (size_t)m * E_DIM + ncol;
                }
                *(float2*)dst = v;
            }
        }
    }
}

__global__ __launch_bounds__(256, 2)
void qkv_tc_kernel(const float* __restrict__ x,
                   const float* __restrict__ wq, const float* __restrict__ bq,
                   const float* __restrict__ wk, const float* __restrict__ bk,
                   const float* __restrict__ wv, const float* __restrict__ bv)
{
    const float* W; const float* bias; float* C;
    if (blockIdx.z == 0)      { W = wq; bias = bq; C = g_Q; }
    else if (blockIdx.z == 1) { W = wk; bias = bk; C = g_K; }
    else                      { W = wv; bias = bv; C = g_V; }
    gemm_tc_body(x, W, bias, C, 1);
}

__global__ __launch_bounds__(256, 2)
void out_tc_kernel(const float* __restrict__ wo, const float* __restrict__ bo,
                   float* __restrict__ out)
{
    gemm_tc_body(g_attn, wo, bo, out, 0);
}

// ===========================================================================
// HMMA flash attention, software-pipelined (double-buffered K/V).
// One CTA per (bh, 128-row q-block), 8 warps, each warp owns 16 q-rows.
// smem elems: Q hi 0 / lo 9216;
//   K buf b: 18432 + b*18432 (hi), +9216 (lo)   [stride 72 per row]
//   V buf b: 55296 + b*17408 (hi), +8704 (lo)   [transposed, stride 136]
// Total 90112 elems = 180224 bytes (1 CTA/SM).
// ===========================================================================
#define FQ_H   0
#define FQ_L   9216
#define FKB(b) (18432 + (b) * 18432)
#define FVB(b) (55296 + (b) * 17408)
#define FL_SMEM_BYTES (90112 * 2)

__global__ __launch_bounds__(256)
void flash_tc_kernel()
{
    extern __shared__ __nv_bfloat16 smb[];
    uint32_t* smw = (uint32_t*)smb;
    const int WQ_H = 0, WQ_L = 4608;

    const int tid  = threadIdx.x;
    const int lane = tid & 31;
    const int wid  = tid >> 5;
    const int fr   = lane >> 2;     // 0..7
    const int fc   = lane & 3;      // 0..3
    const int bh   = blockIdx.y;
    const int q0   = blockIdx.x * 128;

    const float* Qp = g_Q + (size_t)bh * SEQ_LEN * H_DIM;
    const float* Kp = g_K + (size_t)bh * SEQ_LEN * H_DIM;
    const float* Vp = g_V + (size_t)bh * SEQ_LEN * H_DIM;

    // ---- stage Q block (fold 1/sqrt(64) = 0.125), hi/lo split ----
#pragma unroll
    for (int r = 0; r < 8; r++) {
        int idx = tid + r * 256;
        int row = idx >> 4;
        int kc4 = idx & 15;
        float4 a = *(const float4*)(Qp + (size_t)(q0 + row) * H_DIM + kc4 * 4);
        a.x *= 0.125f; a.y *= 0.125f; a.z *= 0.125f; a.w *= 0.125f;
        uint2 hi, lo;
        split_f4(a, hi, lo);
        __nv_bfloat16* dst = smb + FQ_H + row * AST + kc4 * 4;
        *(uint2*)dst          = hi;
        *(uint2*)(dst + FQ_L) = lo;
    }

    // ---- stage K/V tile 0 into buffer 0 (direct) ----
#pragma unroll
    for (int r = 0; r < 8; r++) {
        int idx = tid + r * 256;
        int row = idx >> 4;
        int kc4 = idx & 15;
        float4 a = *(const float4*)(Kp + (size_t)row * H_DIM + kc4 * 4);
        uint2 hi, lo;
        split_f4(a, hi, lo);
        __nv_bfloat16* dst = smb + FKB(0) + row * AST + kc4 * 4;
        *(uint2*)dst         = hi;
        *(uint2*)(dst + 9216) = lo;

        float4 v = *(const float4*)(Vp + (size_t)row * H_DIM + kc4 * 4);
        float vv[4] = {v.x, v.y, v.z, v.w};
#pragma unroll
        for (int j = 0; j < 4; j++) {
            int d = kc4 * 4 + j;
            __nv_bfloat16 hv = __float2bfloat16_rn(vv[j]);
            float lvf = vv[j] - __bfloat162float(hv);
            smb[FVB(0) + d * 136 + row] = hv;
            smb[FVB(0) + 8704 + d * 136 + row] = __float2bfloat16_rn(lvf);
        }
    }

    float m0r = -1e30f, m1r = -1e30f, l0r = 0.0f, l1r = 0.0f;
    float oacc[8][4];
#pragma unroll
    for (int nt = 0; nt < 8; nt++)
#pragma unroll
        for (int i = 0; i < 4; i++) oacc[nt][i] = 0.0f;

    __syncthreads();

    for (int it = 0; it < 16; it++) {
        const int cur = it & 1;
        const int nxt = cur ^ 1;
        const bool has_next = (it < 15);
        const int ktn = (it + 1) * 128;

        const int wkh = 9216 + cur * 9216;          // K hi word base
        const int wkl = wkh + 4608;
        const int wvh = 27648 + cur * 8704;          // V hi word base
        const int wvl = wvh + 4352;

        // ---- prefetch next K tile into registers (hidden under QK MMA) ----
        float4 kreg[8];
        if (has_next) {
#pragma unroll
            for (int r = 0; r < 8; r++) {
                int idx = tid + r * 256;
                int row = idx >> 4;
                int kc4 = idx & 15;
                kreg[r] = *(const float4*)(Kp + (size_t)(ktn + row) * H_DIM + kc4 * 4);
            }
        }

        // ---- S = Q * K^T (3-term split), warp rows wid*16..+15 ----
        float sacc[16][4];
#pragma unroll
        for (int nt = 0; nt < 16; nt++)
#pragma unroll
            for (int i = 0; i < 4; i++) sacc[nt][i] = 0.0f;

#pragma unroll
        for (int ks = 0; ks < 4; ks++) {
            int aI = (wid * 16 + fr) * 36 + ks * 8 + fc;
            uint32_t ah[4], al[4];
            ah[0] = smw[WQ_H + aI];
            ah[1] = smw[WQ_H + aI + 8 * 36];
            ah[2] = smw[WQ_H + aI + 4];
            ah[3] = smw[WQ_H + aI + 8 * 36 + 4];
            al[0] = smw[WQ_L + aI];
            al[1] = smw[WQ_L + aI + 8 * 36];
            al[2] = smw[WQ_L + aI + 4];
            al[3] = smw[WQ_L + aI + 8 * 36 + 4];
#pragma unroll
            for (int nt = 0; nt < 16; nt++) {
                int wI = (nt * 8 + fr) * 36 + ks * 8 + fc;
                uint32_t bh[2], bl[2];
                bh[0] = smw[wkh + wI]; bh[1] = smw[wkh + wI + 4];
                bl[0] = smw[wkl + wI]; bl[1] = smw[wkl + wI + 4];
                mma_bf16(sacc[nt], ah, bh);
                mma_bf16(sacc[nt], al, bh);
                mma_bf16(sacc[nt], ah, bl);
            }
        }

        // ---- store prefetched K into buffer nxt (kreg dies here) ----
        if (has_next) {
#pragma unroll
            for (int r = 0; r < 8; r++) {
                int idx = tid + r * 256;
                int row = idx >> 4;
                int kc4 = idx & 15;
                uint2 hi, lo;
                split_f4(kreg[r], hi, lo);
                __nv_bfloat16* dst = smb + FKB(nxt) + row * AST + kc4 * 4;
                *(uint2*)dst          = hi;
                *(uint2*)(dst + 9216) = lo;
            }
        }

        // ---- prefetch next V tile (hidden under softmax + PV) ----
        float4 vreg[8];
        if (has_next) {
#pragma unroll
            for (int r = 0; r < 8; r++) {
                int idx = tid + r * 256;
                int row = idx >> 4;
                int kc4 = idx & 15;
                vreg[r] = *(const float4*)(Vp + (size_t)(ktn + row) * H_DIM + kc4 * 4);
            }
        }

        // ---- online softmax (rows fr and fr+8 of warp tile) ----
        float mx0 = -1e30f, mx1 = -1e30f;
#pragma unroll
        for (int nt = 0; nt < 16; nt++) {
            mx0 = fmaxf(mx0, fmaxf(sacc[nt][0], sacc[nt][1]));
            mx1 = fmaxf(mx1, fmaxf(sacc[nt][2], sacc[nt][3]));
        }
#pragma unroll
        for (int off = 1; off <= 2; off <<= 1) {
            mx0 = fmaxf(mx0, __shfl_xor_sync(0xffffffffu, mx0, off));
            mx1 = fmaxf(mx1, __shfl_xor_sync(0xffffffffu, mx1, off));
        }
        float mn0 = fmaxf(m0r, mx0), mn1 = fmaxf(m1r, mx1);
        float corr0 = fast_exp(m0r - mn0), corr1 = fast_exp(m1r - mn1);
        m0r = mn0; m1r = mn1;

        float sum0 = 0.0f, sum1 = 0.0f;
#pragma unroll
        for (int nt = 0; nt < 16; nt++) {
            float p0 = fast_exp(sacc[nt][0] - m0r);
            float p1 = fast_exp(sacc[nt][1] - m0r);
            float p2 = fast_exp(sacc[nt][2] - m1r);
            float p3 = fast_exp(sacc[nt][3] - m1r);
            sacc[nt][0] = p0; sacc[nt][1] = p1;
            sacc[nt][2] = p2; sacc[nt][3] = p3;
            sum0 += p0 + p1; sum1 += p2 + p3;
        }
#pragma unroll
        for (int off = 1; off <= 2; off <<= 1) {
            sum0 += __shfl_xor_sync(0xffffffffu, sum0, off);
            sum1 += __shfl_xor_sync(0xffffffffu, sum1, off);
        }
        l0r = l0r * corr0 + sum0;
        l1r = l1r * corr1 + sum1;

#pragma unroll
        for (int nt = 0; nt < 8; nt++) {
            oacc[nt][0] *= corr0; oacc[nt][1] *= corr0;
            oacc[nt][2] *= corr1; oacc[nt][3] *= corr1;
        }

        // ---- O += P * V (3-term split; P from registers) ----
#pragma unroll
        for (int ks = 0; ks < 8; ks++) {
            uint32_t ph[4], pl[4];
            {
                float* t0 = sacc[2 * ks];
                float* t1 = sacc[2 * ks + 1];
                __nv_bfloat162 h;
                float2 bf;
                h = __float22bfloat162_rn(make_float2(t0[0], t0[1]));
                ph[0] = *(uint32_t*)&h; bf = __bfloat1622float2(h);
                h = __float22bfloat162_rn(make_float2(t0[0] - bf.x, t0[1] - bf.y));
                pl[0] = *(uint32_t*)&h;
                h = __float22bfloat162_rn(make_float2(t0[2], t0[3]));
                ph[1] = *(uint32_t*)&h; bf = __bfloat1622float2(h);
                h = __float22bfloat162_rn(make_float2(t0[2] - bf.x, t0[3] - bf.y));
                pl[1] = *(uint32_t*)&h;
                h = __float22bfloat162_rn(make_float2(t1[0], t1[1]));
                ph[2] = *(uint32_t*)&h; bf = __bfloat1622float2(h);
                h = __float22bfloat162_rn(make_float2(t1[0] - bf.x, t1[1] - bf.y));
                pl[2] = *(uint32_t*)&h;
                h = __float22bfloat162_rn(make_float2(t1[2], t1[3]));
                ph[3] = *(uint32_t*)&h; bf = __bfloat1622float2(h);
                h = __float22bfloat162_rn(make_float2(t1[2] - bf.x, t1[3] - bf.y));
                pl[3] = *(uint32_t*)&h;
            }
#pragma unroll
            for (int nt = 0; nt < 8; nt++) {
                int wI = (nt * 8 + fr) * 68 + ks * 8 + fc;
                uint32_t bh[2], bl[2];
                bh[0] = smw[wvh + wI]; bh[1] = smw[wvh + wI + 4];
                bl[0] = smw[wvl + wI]; bl[1] = smw[wvl + wI + 4];
                mma_bf16(oacc[nt], ph, bh);
                mma_bf16(oacc[nt], pl, bh);
                mma_bf16(oacc[nt], ph, bl);
            }
        }

        // ---- store prefetched V (transposed) into buffer nxt ----
        if (has_next) {
#pragma unroll
            for (int r = 0; r < 8; r++) {
                int idx = tid + r * 256;
                int row = idx >> 4;
                int kc4 = idx & 15;
                float vv[4] = {vreg[r].x, vreg[r].y, vreg[r].z, vreg[r].w};
#pragma unroll
                for (int j = 0; j < 4; j++) {
                    int d = kc4 * 4 + j;
                    __nv_bfloat16 hv = __float2bfloat16_rn(vv[j]);
                    float lvf = vv[j] - __bfloat162float(hv);
                    smb[FVB(nxt) + d * 136 + row] = hv;
                    smb[FVB(nxt) + 8704 + d * 136 + row] = __float2bfloat16_rn(lvf);
                }
            }
        }
        __syncthreads();
    }

    // ---- write O/l into [B,S,E] ----
    const int b_ = bh >> 4;
    const int h  = bh & 15;
    float inv0 = 1.0f / l0r, inv1 = 1.0f / l1r;
    int row0 = q0 + wid * 16 + fr;
#pragma unroll
    for (int nt = 0; nt < 8; nt++) {
        int col = h * H_DIM + nt * 8 + fc * 2;
        float* d0 = g_attn + (size_t)(b_ * SEQ_LEN + row0) * E_DIM + col;
        float* d1 = g_attn + (size_t)(b_ * SEQ_LEN + row0 + 8) * E_DIM + col;
        *(float2*)d0 = make_float2(oacc[nt][0] * inv0, oacc[nt][1] * inv0);
        *(float2*)d1 = make_float2(oacc[nt][2] * inv1, oacc[nt][3] * inv1);
    }
}

// ---------------------------------------------------------------------------
extern "C" void kernel_launch(void* const* d_in, const int* in_sizes, int n_in,
                              void* d_out, int out_size)
{
    const float* x  = (const float*)d_in[0];
    const float* wq = (const float*)d_in[1];
    const float* bq = (const float*)d_in[2];
    const float* wk = (const float*)d_in[3];
    const float* bk = (const float*)d_in[4];
    const float* wv = (const float*)d_in[5];
    const float* bv = (const float*)d_in[6];
    const float* wo = (const float*)d_in[7];
    const float* bo = (const float*)d_in[8];
    float* out = (float*)d_out;

    cudaFuncSetAttribute(qkv_tc_kernel,
                         cudaFuncAttributeMaxDynamicSharedMemorySize, GEMM_SMEM);
    cudaFuncSetAttribute(out_tc_kernel,
                         cudaFuncAttributeMaxDynamicSharedMemorySize, GEMM_SMEM);
    cudaFuncSetAttribute(flash_tc_kernel,
                         cudaFuncAttributeMaxDynamicSharedMemorySize, FL_SMEM_BYTES);

    dim3 gqkv(E_DIM / 128, M_TOT / 128, 3);
    qkv_tc_kernel<<<gqkv, 256, GEMM_SMEM>>>(x, wq, bq, wk, bk, wv, bv);

    dim3 gfl(SEQ_LEN / 128, N_BATCH * N_HEADS);
    flash_tc_kernel<<<gfl, 256, FL_SMEM_BYTES>>>();

    dim3 gout(E_DIM / 128, M_TOT / 128);
    out_tc_kernel<<<gout, 256, GEMM_SMEM>>>(wo, bo, out);
}